// round 6
// baseline (speedup 1.0000x reference)
#include <cuda_runtime.h>
#include <math.h>

// Problem constants: B=2, L=1024, H=8, E=64, n_top=35 (5*ceil(ln 1024))
#define B_  2
#define L_  1024
#define H_  8
#define E_  64
#define BH_ 16
#define NT_ 35      // top-k per half
#define NS_ 70      // total selected columns
#define SCALE_ 0.125f

// -------- static scratch (no allocations allowed) --------
__device__ float g_amp2_t[BH_ * L_];            // 64 KB
__device__ int   g_selidx[BH_ * NS_];           // [0..34]=idx_t, [35..69]=idx_tf
__device__ float g_usel[BH_ * 71 * E_];         // row 70 = bias row bv

// ---------------------------------------------------------
__global__ void zero_kernel() {
    int i = blockIdx.x * 256 + threadIdx.x;
    if (i < BH_ * L_)       g_amp2_t[i] = 0.f;
    if (i < BH_ * 71 * E_)  g_usel[i]   = 0.f;
}

__device__ __forceinline__ float2 cmulf(float2 a, float2 b) {
    return make_float2(a.x * b.x - a.y * b.y, a.x * b.y + a.y * b.x);
}

// FFT-based circular correlation per channel (b,h,e).
// z = q + i*k ; Z = FFT(z) ; Qf,Kf via Hermitian split ; P = Qf*conj(Kf)
// ac = Re(FFT(conj(P)))/N  (== irfft of Hermitian P). Accumulate ac^2 per tau.
// Stockham radix-4, 5 stages, 256 threads (one butterfly group each).
__global__ void __launch_bounds__(256) corr_fft_kernel(const float* __restrict__ q,
                                                       const float* __restrict__ k) {
    __shared__ float2 bufA[L_];
    __shared__ float2 bufB[L_];

    int ch = blockIdx.x;            // b*512 + h*64 + e
    int e  = ch & 63;
    int bh = ch >> 6;
    int h  = bh & 7;
    int b  = bh >> 3;
    int tid = threadIdx.x;

    size_t base = (size_t)b * (L_ * H_ * E_) + (size_t)h * E_ + e;
    #pragma unroll
    for (int jj = 0; jj < 4; jj++) {
        int l = tid + jj * 256;
        bufA[l] = make_float2(q[base + (size_t)l * (H_ * E_)],
                              k[base + (size_t)l * (H_ * E_)]);
    }
    __syncthreads();

    float2* X = bufA;
    float2* Y = bufB;

    // ---- forward FFT: 5 radix-4 stages ----
    #pragma unroll
    for (int stage = 0; stage < 5; stage++) {
        int s2 = 2 * stage;
        int Ns = 1 << s2;
        int j = tid;
        float2 v0 = X[j];
        float2 v1 = X[j + 256];
        float2 v2 = X[j + 512];
        float2 v3 = X[j + 768];
        int jm = j & (Ns - 1);
        float ang = -6.28318530717958647692f * (float)jm / (float)(4 * Ns);
        float sn, cs;
        __sincosf(ang, &sn, &cs);
        float2 w1 = make_float2(cs, sn);
        float2 w2 = cmulf(w1, w1);
        float2 w3 = cmulf(w2, w1);
        v1 = cmulf(v1, w1);
        v2 = cmulf(v2, w2);
        v3 = cmulf(v3, w3);
        float2 t0 = make_float2(v0.x + v2.x, v0.y + v2.y);
        float2 t1 = make_float2(v0.x - v2.x, v0.y - v2.y);
        float2 t2 = make_float2(v1.x + v3.x, v1.y + v3.y);
        float2 t3 = make_float2(v1.x - v3.x, v1.y - v3.y);
        int idxD = ((j >> s2) << (s2 + 2)) + jm;
        Y[idxD]          = make_float2(t0.x + t2.x, t0.y + t2.y);   // t0 + t2
        Y[idxD + Ns]     = make_float2(t1.x + t3.y, t1.y - t3.x);   // t1 - i*t3
        Y[idxD + 2 * Ns] = make_float2(t0.x - t2.x, t0.y - t2.y);   // t0 - t2
        Y[idxD + 3 * Ns] = make_float2(t1.x - t3.y, t1.y + t3.x);   // t1 + i*t3
        float2* tmp = X; X = Y; Y = tmp;
        __syncthreads();
    }

    // ---- pointwise: write conj(P) into Y ----
    #pragma unroll
    for (int jj = 0; jj < 4; jj++) {
        int j = tid + jj * 256;
        float2 z  = X[j];
        float2 zn = X[(L_ - j) & (L_ - 1)];
        // Qf = (z + conj(zn))/2 ; Kf = (z - conj(zn))/(2i)
        float2 Qf = make_float2(0.5f * (z.x + zn.x), 0.5f * (z.y - zn.y));
        float2 Kf = make_float2(0.5f * (z.y + zn.y), -0.5f * (z.x - zn.x));
        // P = Qf * conj(Kf)
        float px = Qf.x * Kf.x + Qf.y * Kf.y;
        float py = Qf.y * Kf.x - Qf.x * Kf.y;
        Y[j] = make_float2(px, -py);   // conj(P)
    }
    __syncthreads();
    { float2* tmp = X; X = Y; Y = tmp; }   // X -> conj(P)

    // ---- second forward FFT (gives conj(N*ifft(P))) ----
    #pragma unroll
    for (int stage = 0; stage < 5; stage++) {
        int s2 = 2 * stage;
        int Ns = 1 << s2;
        int j = tid;
        float2 v0 = X[j];
        float2 v1 = X[j + 256];
        float2 v2 = X[j + 512];
        float2 v3 = X[j + 768];
        int jm = j & (Ns - 1);
        float ang = -6.28318530717958647692f * (float)jm / (float)(4 * Ns);
        float sn, cs;
        __sincosf(ang, &sn, &cs);
        float2 w1 = make_float2(cs, sn);
        float2 w2 = cmulf(w1, w1);
        float2 w3 = cmulf(w2, w1);
        v1 = cmulf(v1, w1);
        v2 = cmulf(v2, w2);
        v3 = cmulf(v3, w3);
        float2 t0 = make_float2(v0.x + v2.x, v0.y + v2.y);
        float2 t1 = make_float2(v0.x - v2.x, v0.y - v2.y);
        float2 t2 = make_float2(v1.x + v3.x, v1.y + v3.y);
        float2 t3 = make_float2(v1.x - v3.x, v1.y - v3.y);
        int idxD = ((j >> s2) << (s2 + 2)) + jm;
        Y[idxD]          = make_float2(t0.x + t2.x, t0.y + t2.y);
        Y[idxD + Ns]     = make_float2(t1.x + t3.y, t1.y - t3.x);
        Y[idxD + 2 * Ns] = make_float2(t0.x - t2.x, t0.y - t2.y);
        Y[idxD + 3 * Ns] = make_float2(t1.x - t3.y, t1.y + t3.x);
        float2* tmp = X; X = Y; Y = tmp;
        __syncthreads();
    }

    // ac[tau] = X[tau].x / N ; accumulate ac^2
    float* amp = g_amp2_t + bh * L_;
    #pragma unroll
    for (int jj = 0; jj < 4; jj++) {
        int t = tid + jj * 256;
        float ac = X[t].x * (1.0f / (float)L_);
        atomicAdd(amp + t, ac * ac);
    }
}

// Top-35 per (b,h). blockIdx.x = bh + 16*which (0: corr amps, 1: tf norms).
// Values live in 4 registers per thread (l = tid + 256*jj). Per round:
// thread-local argmax -> warp shfl reduce -> 8-way smem reduce (all threads).
// Ties broken toward lower l index (matches lax.top_k set semantics).
__global__ void __launch_bounds__(256) topk_kernel(const float* __restrict__ tfq) {
    int bh    = blockIdx.x & 15;
    int which = blockIdx.x >> 4;
    int tid = threadIdx.x;
    int lane = tid & 31, wrp = tid >> 5;

    float v[4];
    if (which == 0) {
        #pragma unroll
        for (int jj = 0; jj < 4; jj++)
            v[jj] = g_amp2_t[bh * L_ + tid + jj * 256];
    } else {
        int b = bh >> 3, h = bh & 7;
        #pragma unroll
        for (int jj = 0; jj < 4; jj++) {
            int l = tid + jj * 256;
            const float4* p = (const float4*)(tfq + (((size_t)(b * L_ + l) * H_ + h) * E_));
            float s = 0.f;
            #pragma unroll
            for (int j = 0; j < 16; j++) {
                float4 x = p[j];
                s += x.x * x.x + x.y * x.y + x.z * x.z + x.w * x.w;
            }
            v[jj] = s;
        }
    }

    __shared__ float sv[8];
    __shared__ int   si[8];

    for (int iter = 0; iter < NT_; iter++) {
        float best = v[0];
        int   bi   = tid;
        #pragma unroll
        for (int jj = 1; jj < 4; jj++) {
            if (v[jj] > best) { best = v[jj]; bi = tid + jj * 256; }
        }
        #pragma unroll
        for (int off = 16; off > 0; off >>= 1) {
            float ov = __shfl_down_sync(0xffffffffu, best, off);
            int   oi = __shfl_down_sync(0xffffffffu, bi,   off);
            if (ov > best || (ov == best && oi < bi)) { best = ov; bi = oi; }
        }
        if (lane == 0) { sv[wrp] = best; si[wrp] = bi; }
        __syncthreads();
        float wv = sv[0]; int wi = si[0];
        #pragma unroll
        for (int w = 1; w < 8; w++) {
            if (sv[w] > wv || (sv[w] == wv && si[w] < wi)) { wv = sv[w]; wi = si[w]; }
        }
        if (tid == 0) g_selidx[bh * NS_ + which * NT_ + iter] = wi;
        if ((wi & 255) == tid) v[wi >> 8] = -1.0f;
        __syncthreads();
    }
}

// Gathered U columns + bias row: usel[bh][i][d] = sum_m W[m, c_i] * V[b,m,h,d],
// row 70: sum_m bias[m]*V[b,m,h,d]. grid (mchunk=16, bh=16), 512 threads.
// Gather has ~9 independent scattered loads per thread (MLP); compute split
// over 8 i-groups; atomic partial sums into g_usel (16 adds per address).
__global__ void __launch_bounds__(512) usel_kernel(const float* __restrict__ W,
                                                   const float* __restrict__ bias,
                                                   const float* __restrict__ V) {
    int bh = blockIdx.y, b = bh >> 3, h = bh & 7;
    int m0 = blockIdx.x * 64;
    __shared__ float ws[71][64];
    __shared__ float vs[64][64];
    __shared__ int   cs_[NS_];
    int tid = threadIdx.x;

    if (tid < NS_) {
        cs_[tid] = g_selidx[bh * NS_ + tid] + ((tid >= NT_) ? L_ : 0);
    }
    // V tile: coalesced float4 loads (64*64 floats = 1024 float4, 2/thread)
    {
        const float4* vsrc = (const float4*)(V + (((size_t)(b * L_ + m0) * H_) + h) * E_);
        // rows m0+mm have stride H_*E_/4 = 128 float4; row layout: mm = idx>>4, c4 = idx&15
        #pragma unroll
        for (int t = 0; t < 2; t++) {
            int idx = tid + t * 512;
            int mm = idx >> 4, c4 = idx & 15;
            ((float4*)vs)[idx] = vsrc[(size_t)mm * 128 + c4];
        }
    }
    __syncthreads();   // cs_ ready before gather

    // W gather: 71*64 = 4544 scattered loads over 512 threads (8-9 each, independent)
    for (int idx = tid; idx < 71 * 64; idx += 512) {
        int i = idx >> 6, mm = idx & 63;
        float v;
        if (i < NS_) {
            v = __ldg(&W[(size_t)(m0 + mm) * (2 * L_) + cs_[i]]);
        } else {
            v = bias[m0 + mm];
        }
        ws[i][mm] = v;
    }
    __syncthreads();

    int d = tid & 63, ig = tid >> 6;   // 8 i-groups
    float acc[9];
    #pragma unroll
    for (int kk2 = 0; kk2 < 9; kk2++) acc[kk2] = 0.f;

    for (int mm = 0; mm < 64; mm++) {
        float v = vs[mm][d];
        #pragma unroll
        for (int kk2 = 0; kk2 < 9; kk2++) {
            int i = ig + kk2 * 8;
            if (i < 71) acc[kk2] += ws[i][mm] * v;
        }
    }
    #pragma unroll
    for (int kk2 = 0; kk2 < 9; kk2++) {
        int i = ig + kk2 * 8;
        if (i < 71) atomicAdd(&g_usel[(size_t)(bh * 71 + i) * E_ + d], acc[kk2]);
    }
}

// Fused scores + softmax + combine. One block = 32 l values of one (b,h), 256 threads.
// Phase 1 (8 groups of 32 = half x iseg(4)): s[i][l] = scale * <sel_i, row_l>
// Phase 2 (8 d-groups x 32 l): softmax over the 70 finite scores, then
//   out[l][d] = sum_i p_i * usel[i][d] + bias_row[d].
__global__ void __launch_bounds__(256) fused_kernel(const float* __restrict__ tfq,
                                                    const float* __restrict__ q,
                                                    const float* __restrict__ kk,
                                                    float* __restrict__ out) {
    int bh = blockIdx.y, b = bh >> 3, h = bh & 7;
    int tid = threadIdx.x;
    int lane = tid & 31;

    __shared__ float qsel[NS_ * E_];    // selected query rows
    __shared__ float us[71 * E_];       // gathered U columns + bias row
    __shared__ float s[NS_][32];        // scores for this l-tile

    for (int idx = tid; idx < NS_ * E_; idx += 256) {
        int i = idx >> 6, e = idx & 63;
        int src = g_selidx[bh * NS_ + i];
        const float* sp = (i < NT_) ? q : tfq;
        qsel[idx] = sp[(((size_t)(b * L_ + src) * H_) + h) * E_ + e];
    }
    for (int idx = tid; idx < 71 * E_; idx += 256)
        us[idx] = g_usel[(size_t)bh * 71 * E_ + idx];
    __syncthreads();

    // ---- phase 1: scores ----
    {
        int g = tid >> 5;
        int half = g >> 2;              // 0: vs keys, 1: vs tf_queries
        int iseg = g & 3;
        int i0 = iseg * 9;
        int i1 = (i0 + 9 < NT_) ? (i0 + 9) : NT_;
        int l = blockIdx.x * 32 + lane;

        const float* row = ((half == 0) ? kk : tfq) + (((size_t)(b * L_ + l) * H_) + h) * E_;
        float4 r[16];
        #pragma unroll
        for (int j = 0; j < 16; j++) r[j] = ((const float4*)row)[j];

        for (int i = i0; i < i1; i++) {
            const float4* qr = (const float4*)&qsel[(half * NT_ + i) * E_];
            float s0 = 0.f, s1 = 0.f;
            #pragma unroll
            for (int j = 0; j < 8; j++) {
                float4 qa = qr[j];
                float4 qb = qr[j + 8];
                s0 += qa.x * r[j].x + qa.y * r[j].y + qa.z * r[j].z + qa.w * r[j].w;
                s1 += qb.x * r[j + 8].x + qb.y * r[j + 8].y + qb.z * r[j + 8].z + qb.w * r[j + 8].w;
            }
            s[half * NT_ + i][lane] = (s0 + s1) * SCALE_;
        }
    }
    __syncthreads();

    // ---- phase 2: softmax + combine (8 d per thread) ----
    {
        int dg = tid >> 5;              // 8 d-values per group
        int d0 = dg * 8;
        int l = blockIdx.x * 32 + lane;

        float mx = -1e30f;
        #pragma unroll
        for (int i = 0; i < NS_; i++) mx = fmaxf(mx, s[i][lane]);

        float4 acc0 = make_float4(0.f, 0.f, 0.f, 0.f);
        float4 acc1 = make_float4(0.f, 0.f, 0.f, 0.f);
        float ssum = 0.f;

        for (int i = 0; i < NS_; i++) {
            float p = __expf(s[i][lane] - mx);
            ssum += p;
            const float4* u4 = (const float4*)&us[i * E_ + d0];
            float4 ua = u4[0], ub = u4[1];
            acc0.x += p * ua.x; acc0.y += p * ua.y; acc0.z += p * ua.z; acc0.w += p * ua.w;
            acc1.x += p * ub.x; acc1.y += p * ub.y; acc1.z += p * ub.z; acc1.w += p * ub.w;
        }
        float inv = 1.f / ssum;
        const float4* bv = (const float4*)&us[NS_ * E_ + d0];
        float4 b0 = bv[0], b1 = bv[1];
        float4* op = (float4*)(out + (((size_t)(b * L_ + l) * H_) + h) * E_ + d0);
        op[0] = make_float4(acc0.x * inv + b0.x, acc0.y * inv + b0.y,
                            acc0.z * inv + b0.z, acc0.w * inv + b0.w);
        op[1] = make_float4(acc1.x * inv + b1.x, acc1.y * inv + b1.y,
                            acc1.z * inv + b1.z, acc1.w * inv + b1.w);
    }
}

extern "C" void kernel_launch(void* const* d_in, const int* in_sizes, int n_in,
                              void* d_out, int out_size) {
    const float* tfq  = (const float*)d_in[0];
    const float* q    = (const float*)d_in[1];
    const float* k    = (const float*)d_in[2];
    const float* v    = (const float*)d_in[3];
    // d_in[4] = mask (unused)
    const float* W    = (const float*)d_in[5];
    const float* bias = (const float*)d_in[6];
    float* out = (float*)d_out;

    zero_kernel<<<(BH_ * 71 * E_ + 255) / 256, 256>>>();
    corr_fft_kernel<<<BH_ * E_, 256>>>(q, k);
    topk_kernel<<<32, 256>>>(tfq);
    usel_kernel<<<dim3(16, BH_), 512>>>(W, bias, v);
    fused_kernel<<<dim3(32, BH_), 256>>>(tfq, q, k, out);
}

// round 7
// speedup vs baseline: 1.1258x; 1.1258x over previous
#include <cuda_runtime.h>
#include <math.h>

// Problem constants: B=2, L=1024, H=8, E=64, n_top=35 (5*ceil(ln 1024))
#define B_  2
#define L_  1024
#define H_  8
#define E_  64
#define BH_ 16
#define NT_ 35      // top-k per half
#define NS_ 70      // total selected columns
#define SCALE_ 0.125f

// -------- static scratch (no allocations allowed) --------
__device__ float g_amp2_t[BH_ * L_];            // 64 KB
__device__ int   g_selidx[BH_ * NS_];           // [0..34]=idx_t, [35..69]=idx_tf
__device__ float g_usel[BH_ * 71 * E_];         // row 70 = bias row bv

// ---------------------------------------------------------
__global__ void zero_kernel() {
    int i = blockIdx.x * 256 + threadIdx.x;
    if (i < BH_ * L_)       g_amp2_t[i] = 0.f;
    if (i < BH_ * 71 * E_)  g_usel[i]   = 0.f;
}

__device__ __forceinline__ float2 cmulf(float2 a, float2 b) {
    return make_float2(a.x * b.x - a.y * b.y, a.x * b.y + a.y * b.x);
}

// FFT-based circular correlation per channel (b,h,e).
// z = q + i*k ; Z = FFT(z) ; Qf,Kf via Hermitian split ; P = Qf*conj(Kf)
// ac = Re(FFT(conj(P)))/N  (== irfft of Hermitian P). Accumulate ac^2 per tau.
// Stockham radix-4, 5 stages, 256 threads (one butterfly group each).
__global__ void __launch_bounds__(256) corr_fft_kernel(const float* __restrict__ q,
                                                       const float* __restrict__ k) {
    __shared__ float2 bufA[L_];
    __shared__ float2 bufB[L_];

    int ch = blockIdx.x;            // b*512 + h*64 + e
    int e  = ch & 63;
    int bh = ch >> 6;
    int h  = bh & 7;
    int b  = bh >> 3;
    int tid = threadIdx.x;

    size_t base = (size_t)b * (L_ * H_ * E_) + (size_t)h * E_ + e;
    #pragma unroll
    for (int jj = 0; jj < 4; jj++) {
        int l = tid + jj * 256;
        bufA[l] = make_float2(q[base + (size_t)l * (H_ * E_)],
                              k[base + (size_t)l * (H_ * E_)]);
    }
    __syncthreads();

    float2* X = bufA;
    float2* Y = bufB;

    // ---- forward FFT: 5 radix-4 stages ----
    #pragma unroll
    for (int stage = 0; stage < 5; stage++) {
        int s2 = 2 * stage;
        int Ns = 1 << s2;
        int j = tid;
        float2 v0 = X[j];
        float2 v1 = X[j + 256];
        float2 v2 = X[j + 512];
        float2 v3 = X[j + 768];
        int jm = j & (Ns - 1);
        float ang = -6.28318530717958647692f * (float)jm / (float)(4 * Ns);
        float sn, cs;
        __sincosf(ang, &sn, &cs);
        float2 w1 = make_float2(cs, sn);
        float2 w2 = cmulf(w1, w1);
        float2 w3 = cmulf(w2, w1);
        v1 = cmulf(v1, w1);
        v2 = cmulf(v2, w2);
        v3 = cmulf(v3, w3);
        float2 t0 = make_float2(v0.x + v2.x, v0.y + v2.y);
        float2 t1 = make_float2(v0.x - v2.x, v0.y - v2.y);
        float2 t2 = make_float2(v1.x + v3.x, v1.y + v3.y);
        float2 t3 = make_float2(v1.x - v3.x, v1.y - v3.y);
        int idxD = ((j >> s2) << (s2 + 2)) + jm;
        Y[idxD]          = make_float2(t0.x + t2.x, t0.y + t2.y);   // t0 + t2
        Y[idxD + Ns]     = make_float2(t1.x + t3.y, t1.y - t3.x);   // t1 - i*t3
        Y[idxD + 2 * Ns] = make_float2(t0.x - t2.x, t0.y - t2.y);   // t0 - t2
        Y[idxD + 3 * Ns] = make_float2(t1.x - t3.y, t1.y + t3.x);   // t1 + i*t3
        float2* tmp = X; X = Y; Y = tmp;
        __syncthreads();
    }

    // ---- pointwise: write conj(P) into Y ----
    #pragma unroll
    for (int jj = 0; jj < 4; jj++) {
        int j = tid + jj * 256;
        float2 z  = X[j];
        float2 zn = X[(L_ - j) & (L_ - 1)];
        // Qf = (z + conj(zn))/2 ; Kf = (z - conj(zn))/(2i)
        float2 Qf = make_float2(0.5f * (z.x + zn.x), 0.5f * (z.y - zn.y));
        float2 Kf = make_float2(0.5f * (z.y + zn.y), -0.5f * (z.x - zn.x));
        // P = Qf * conj(Kf)
        float px = Qf.x * Kf.x + Qf.y * Kf.y;
        float py = Qf.y * Kf.x - Qf.x * Kf.y;
        Y[j] = make_float2(px, -py);   // conj(P)
    }
    __syncthreads();
    { float2* tmp = X; X = Y; Y = tmp; }   // X -> conj(P)

    // ---- second forward FFT (gives conj(N*ifft(P))) ----
    #pragma unroll
    for (int stage = 0; stage < 5; stage++) {
        int s2 = 2 * stage;
        int Ns = 1 << s2;
        int j = tid;
        float2 v0 = X[j];
        float2 v1 = X[j + 256];
        float2 v2 = X[j + 512];
        float2 v3 = X[j + 768];
        int jm = j & (Ns - 1);
        float ang = -6.28318530717958647692f * (float)jm / (float)(4 * Ns);
        float sn, cs;
        __sincosf(ang, &sn, &cs);
        float2 w1 = make_float2(cs, sn);
        float2 w2 = cmulf(w1, w1);
        float2 w3 = cmulf(w2, w1);
        v1 = cmulf(v1, w1);
        v2 = cmulf(v2, w2);
        v3 = cmulf(v3, w3);
        float2 t0 = make_float2(v0.x + v2.x, v0.y + v2.y);
        float2 t1 = make_float2(v0.x - v2.x, v0.y - v2.y);
        float2 t2 = make_float2(v1.x + v3.x, v1.y + v3.y);
        float2 t3 = make_float2(v1.x - v3.x, v1.y - v3.y);
        int idxD = ((j >> s2) << (s2 + 2)) + jm;
        Y[idxD]          = make_float2(t0.x + t2.x, t0.y + t2.y);
        Y[idxD + Ns]     = make_float2(t1.x + t3.y, t1.y - t3.x);
        Y[idxD + 2 * Ns] = make_float2(t0.x - t2.x, t0.y - t2.y);
        Y[idxD + 3 * Ns] = make_float2(t1.x - t3.y, t1.y + t3.x);
        float2* tmp = X; X = Y; Y = tmp;
        __syncthreads();
    }

    // ac[tau] = X[tau].x / N ; accumulate ac^2
    float* amp = g_amp2_t + bh * L_;
    #pragma unroll
    for (int jj = 0; jj < 4; jj++) {
        int t = tid + jj * 256;
        float ac = X[t].x * (1.0f / (float)L_);
        atomicAdd(amp + t, ac * ac);
    }
}

// Top-35 per (b,h). blockIdx.x = bh + 16*which (0: corr amps, 1: tf norms).
// Values live in 4 registers per thread (l = tid + 256*jj). Per round:
// thread-local argmax -> warp shfl reduce -> 8-way smem reduce (all threads).
// Ties broken toward lower l index (matches lax.top_k set semantics).
__global__ void __launch_bounds__(256) topk_kernel(const float* __restrict__ tfq) {
    int bh    = blockIdx.x & 15;
    int which = blockIdx.x >> 4;
    int tid = threadIdx.x;
    int lane = tid & 31, wrp = tid >> 5;

    float v[4];
    if (which == 0) {
        #pragma unroll
        for (int jj = 0; jj < 4; jj++)
            v[jj] = g_amp2_t[bh * L_ + tid + jj * 256];
    } else {
        int b = bh >> 3, h = bh & 7;
        #pragma unroll
        for (int jj = 0; jj < 4; jj++) {
            int l = tid + jj * 256;
            const float4* p = (const float4*)(tfq + (((size_t)(b * L_ + l) * H_ + h) * E_));
            float s = 0.f;
            #pragma unroll
            for (int j = 0; j < 16; j++) {
                float4 x = p[j];
                s += x.x * x.x + x.y * x.y + x.z * x.z + x.w * x.w;
            }
            v[jj] = s;
        }
    }

    __shared__ float sv[8];
    __shared__ int   si[8];

    for (int iter = 0; iter < NT_; iter++) {
        float best = v[0];
        int   bi   = tid;
        #pragma unroll
        for (int jj = 1; jj < 4; jj++) {
            if (v[jj] > best) { best = v[jj]; bi = tid + jj * 256; }
        }
        #pragma unroll
        for (int off = 16; off > 0; off >>= 1) {
            float ov = __shfl_down_sync(0xffffffffu, best, off);
            int   oi = __shfl_down_sync(0xffffffffu, bi,   off);
            if (ov > best || (ov == best && oi < bi)) { best = ov; bi = oi; }
        }
        if (lane == 0) { sv[wrp] = best; si[wrp] = bi; }
        __syncthreads();
        float wv = sv[0]; int wi = si[0];
        #pragma unroll
        for (int w = 1; w < 8; w++) {
            if (sv[w] > wv || (sv[w] == wv && si[w] < wi)) { wv = sv[w]; wi = si[w]; }
        }
        if (tid == 0) g_selidx[bh * NS_ + which * NT_ + iter] = wi;
        if ((wi & 255) == tid) v[wi >> 8] = -1.0f;
        __syncthreads();
    }
}

// Gathered U columns + bias row: usel[bh][i][d] = sum_m W[m, c_i] * V[b,m,h,d],
// row 70: sum_m bias[m]*V[b,m,h,d]. grid (mchunk=16, bh=16), 512 threads.
// (R6-measured: 21.1us, occ 38.7%) Gather has ~9 independent scattered loads
// per thread (MLP); compute split over 8 i-groups; atomic partial sums.
__global__ void __launch_bounds__(512) usel_kernel(const float* __restrict__ W,
                                                   const float* __restrict__ bias,
                                                   const float* __restrict__ V) {
    int bh = blockIdx.y, b = bh >> 3, h = bh & 7;
    int m0 = blockIdx.x * 64;
    __shared__ float ws[71][64];
    __shared__ float vs[64][64];
    __shared__ int   cs_[NS_];
    int tid = threadIdx.x;

    if (tid < NS_) {
        cs_[tid] = g_selidx[bh * NS_ + tid] + ((tid >= NT_) ? L_ : 0);
    }
    // V tile: coalesced float4 loads (64*64 floats = 1024 float4, 2/thread)
    {
        const float4* vsrc = (const float4*)(V + (((size_t)(b * L_ + m0) * H_) + h) * E_);
        #pragma unroll
        for (int t = 0; t < 2; t++) {
            int idx = tid + t * 512;
            int mm = idx >> 4, c4 = idx & 15;
            ((float4*)vs)[idx] = vsrc[(size_t)mm * 128 + c4];
        }
    }
    __syncthreads();   // cs_ ready before gather

    // W gather: 71*64 = 4544 scattered loads over 512 threads (8-9 each, independent)
    for (int idx = tid; idx < 71 * 64; idx += 512) {
        int i = idx >> 6, mm = idx & 63;
        float v;
        if (i < NS_) {
            v = __ldg(&W[(size_t)(m0 + mm) * (2 * L_) + cs_[i]]);
        } else {
            v = bias[m0 + mm];
        }
        ws[i][mm] = v;
    }
    __syncthreads();

    int d = tid & 63, ig = tid >> 6;   // 8 i-groups
    float acc[9];
    #pragma unroll
    for (int kk2 = 0; kk2 < 9; kk2++) acc[kk2] = 0.f;

    for (int mm = 0; mm < 64; mm++) {
        float v = vs[mm][d];
        #pragma unroll
        for (int kk2 = 0; kk2 < 9; kk2++) {
            int i = ig + kk2 * 8;
            if (i < 71) acc[kk2] += ws[i][mm] * v;
        }
    }
    #pragma unroll
    for (int kk2 = 0; kk2 < 9; kk2++) {
        int i = ig + kk2 * 8;
        if (i < 71) atomicAdd(&g_usel[(size_t)(bh * 71 + i) * E_ + d], acc[kk2]);
    }
}

// Fused scores + softmax + combine (R4 128-thread version; part of the 92.4us best).
// One block = 32 l values of one (b,h).
// Phase 1 (4 groups of 32 threads = half x iseg): s[i][l] = scale * <sel_i, row_l>
// Phase 2 (4 d-groups x 32 l): softmax over the 70 finite scores, then
//   out[l][d] = sum_i p_i * usel[i][d] + bias_row[d].
__global__ void __launch_bounds__(128) fused_kernel(const float* __restrict__ tfq,
                                                    const float* __restrict__ q,
                                                    const float* __restrict__ kk,
                                                    float* __restrict__ out) {
    int bh = blockIdx.y, b = bh >> 3, h = bh & 7;
    int tid = threadIdx.x;
    int lane = tid & 31;

    __shared__ float qsel[NS_ * E_];    // selected query rows
    __shared__ float us[71 * E_];       // gathered U columns + bias row
    __shared__ float s[NS_][32];        // scores for this l-tile

    for (int idx = tid; idx < NS_ * E_; idx += 128) {
        int i = idx >> 6, e = idx & 63;
        int src = g_selidx[bh * NS_ + i];
        const float* sp = (i < NT_) ? q : tfq;
        qsel[idx] = sp[(((size_t)(b * L_ + src) * H_) + h) * E_ + e];
    }
    for (int idx = tid; idx < 71 * E_; idx += 128)
        us[idx] = g_usel[(size_t)bh * 71 * E_ + idx];
    __syncthreads();

    // ---- phase 1: scores ----
    {
        int g = tid >> 5;
        int half = g >> 1;              // 0: vs keys, 1: vs tf_queries
        int iseg = g & 1;
        int i0 = iseg ? 18 : 0;
        int i1 = iseg ? NT_ : 18;
        int l = blockIdx.x * 32 + lane;

        const float* row = ((half == 0) ? kk : tfq) + (((size_t)(b * L_ + l) * H_) + h) * E_;
        float4 r[16];
        #pragma unroll
        for (int j = 0; j < 16; j++) r[j] = ((const float4*)row)[j];

        for (int i = i0; i < i1; i++) {
            const float4* qr = (const float4*)&qsel[(half * NT_ + i) * E_];
            float s0 = 0.f, s1 = 0.f;
            #pragma unroll
            for (int j = 0; j < 8; j++) {
                float4 qa = qr[j];
                float4 qb = qr[j + 8];
                s0 += qa.x * r[j].x + qa.y * r[j].y + qa.z * r[j].z + qa.w * r[j].w;
                s1 += qb.x * r[j + 8].x + qb.y * r[j + 8].y + qb.z * r[j + 8].z + qb.w * r[j + 8].w;
            }
            s[half * NT_ + i][lane] = (s0 + s1) * SCALE_;
        }
    }
    __syncthreads();

    // ---- phase 2: softmax + combine ----
    {
        int dg = tid >> 5;              // 16 d-values per group
        int l = blockIdx.x * 32 + lane;

        float mx = -1e30f;
        #pragma unroll
        for (int i = 0; i < NS_; i++) mx = fmaxf(mx, s[i][lane]);

        float4 acc[4];
        #pragma unroll
        for (int j = 0; j < 4; j++) acc[j] = make_float4(0.f, 0.f, 0.f, 0.f);
        float ssum = 0.f;

        for (int i = 0; i < NS_; i++) {
            float p = __expf(s[i][lane] - mx);
            ssum += p;
            const float4* u4 = (const float4*)&us[i * E_ + dg * 16];
            #pragma unroll
            for (int j = 0; j < 4; j++) {
                float4 u = u4[j];
                acc[j].x += p * u.x; acc[j].y += p * u.y;
                acc[j].z += p * u.z; acc[j].w += p * u.w;
            }
        }
        float inv = 1.f / ssum;
        const float4* bv = (const float4*)&us[NS_ * E_ + dg * 16];
        float4* op = (float4*)(out + (((size_t)(b * L_ + l) * H_) + h) * E_ + dg * 16);
        #pragma unroll
        for (int j = 0; j < 4; j++) {
            float4 bb = bv[j];
            op[j] = make_float4(acc[j].x * inv + bb.x, acc[j].y * inv + bb.y,
                                acc[j].z * inv + bb.z, acc[j].w * inv + bb.w);
        }
    }
}

extern "C" void kernel_launch(void* const* d_in, const int* in_sizes, int n_in,
                              void* d_out, int out_size) {
    const float* tfq  = (const float*)d_in[0];
    const float* q    = (const float*)d_in[1];
    const float* k    = (const float*)d_in[2];
    const float* v    = (const float*)d_in[3];
    // d_in[4] = mask (unused)
    const float* W    = (const float*)d_in[5];
    const float* bias = (const float*)d_in[6];
    float* out = (float*)d_out;

    zero_kernel<<<(BH_ * 71 * E_ + 255) / 256, 256>>>();
    corr_fft_kernel<<<BH_ * E_, 256>>>(q, k);
    topk_kernel<<<32, 256>>>(tfq);
    usel_kernel<<<dim3(16, BH_), 512>>>(W, bias, v);
    fused_kernel<<<dim3(32, BH_), 128>>>(tfq, q, k, out);
}

// round 10
// speedup vs baseline: 1.1266x; 1.0007x over previous
#include <cuda_runtime.h>
#include <math.h>

// Problem constants: B=2, L=1024, H=8, E=64, n_top=35 (5*ceil(ln 1024))
#define B_  2
#define L_  1024
#define H_  8
#define E_  64
#define BH_ 16
#define NT_ 35      // top-k per half
#define NS_ 70      // total selected columns
#define SCALE_ 0.125f

// -------- static scratch (no allocations allowed) --------
__device__ float g_amp2_t[BH_ * L_];            // 64 KB
__device__ int   g_selidx[BH_ * NS_];           // [0..34]=idx_t, [35..69]=idx_tf
__device__ float g_usel[BH_ * 71 * E_];         // row 70 = bias row bv

// ---------------------------------------------------------
__global__ void zero_kernel() {
    int i = blockIdx.x * 256 + threadIdx.x;
    if (i < BH_ * L_)       g_amp2_t[i] = 0.f;
    if (i < BH_ * 71 * E_)  g_usel[i]   = 0.f;
}

__device__ __forceinline__ float2 cmulf(float2 a, float2 b) {
    return make_float2(a.x * b.x - a.y * b.y, a.x * b.y + a.y * b.x);
}

// FFT-based circular correlation per channel (b,h,e).
// z = q + i*k ; Z = FFT(z) ; Qf,Kf via Hermitian split ; P = Qf*conj(Kf)
// ac = Re(FFT(conj(P)))/N. Accumulate ac^2 per tau. Stockham radix-4.
__global__ void __launch_bounds__(256) corr_fft_kernel(const float* __restrict__ q,
                                                       const float* __restrict__ k) {
    __shared__ float2 bufA[L_];
    __shared__ float2 bufB[L_];

    int ch = blockIdx.x;            // b*512 + h*64 + e
    int e  = ch & 63;
    int bh = ch >> 6;
    int h  = bh & 7;
    int b  = bh >> 3;
    int tid = threadIdx.x;

    size_t base = (size_t)b * (L_ * H_ * E_) + (size_t)h * E_ + e;
    #pragma unroll
    for (int jj = 0; jj < 4; jj++) {
        int l = tid + jj * 256;
        bufA[l] = make_float2(q[base + (size_t)l * (H_ * E_)],
                              k[base + (size_t)l * (H_ * E_)]);
    }
    __syncthreads();

    float2* X = bufA;
    float2* Y = bufB;

    #pragma unroll
    for (int stage = 0; stage < 5; stage++) {
        int s2 = 2 * stage;
        int Ns = 1 << s2;
        int j = tid;
        float2 v0 = X[j];
        float2 v1 = X[j + 256];
        float2 v2 = X[j + 512];
        float2 v3 = X[j + 768];
        int jm = j & (Ns - 1);
        float ang = -6.28318530717958647692f * (float)jm / (float)(4 * Ns);
        float sn, cs;
        __sincosf(ang, &sn, &cs);
        float2 w1 = make_float2(cs, sn);
        float2 w2 = cmulf(w1, w1);
        float2 w3 = cmulf(w2, w1);
        v1 = cmulf(v1, w1);
        v2 = cmulf(v2, w2);
        v3 = cmulf(v3, w3);
        float2 t0 = make_float2(v0.x + v2.x, v0.y + v2.y);
        float2 t1 = make_float2(v0.x - v2.x, v0.y - v2.y);
        float2 t2 = make_float2(v1.x + v3.x, v1.y + v3.y);
        float2 t3 = make_float2(v1.x - v3.x, v1.y - v3.y);
        int idxD = ((j >> s2) << (s2 + 2)) + jm;
        Y[idxD]          = make_float2(t0.x + t2.x, t0.y + t2.y);
        Y[idxD + Ns]     = make_float2(t1.x + t3.y, t1.y - t3.x);
        Y[idxD + 2 * Ns] = make_float2(t0.x - t2.x, t0.y - t2.y);
        Y[idxD + 3 * Ns] = make_float2(t1.x - t3.y, t1.y + t3.x);
        float2* tmp = X; X = Y; Y = tmp;
        __syncthreads();
    }

    #pragma unroll
    for (int jj = 0; jj < 4; jj++) {
        int j = tid + jj * 256;
        float2 z  = X[j];
        float2 zn = X[(L_ - j) & (L_ - 1)];
        float2 Qf = make_float2(0.5f * (z.x + zn.x), 0.5f * (z.y - zn.y));
        float2 Kf = make_float2(0.5f * (z.y + zn.y), -0.5f * (z.x - zn.x));
        float px = Qf.x * Kf.x + Qf.y * Kf.y;
        float py = Qf.y * Kf.x - Qf.x * Kf.y;
        Y[j] = make_float2(px, -py);   // conj(P)
    }
    __syncthreads();
    { float2* tmp = X; X = Y; Y = tmp; }

    #pragma unroll
    for (int stage = 0; stage < 5; stage++) {
        int s2 = 2 * stage;
        int Ns = 1 << s2;
        int j = tid;
        float2 v0 = X[j];
        float2 v1 = X[j + 256];
        float2 v2 = X[j + 512];
        float2 v3 = X[j + 768];
        int jm = j & (Ns - 1);
        float ang = -6.28318530717958647692f * (float)jm / (float)(4 * Ns);
        float sn, cs;
        __sincosf(ang, &sn, &cs);
        float2 w1 = make_float2(cs, sn);
        float2 w2 = cmulf(w1, w1);
        float2 w3 = cmulf(w2, w1);
        v1 = cmulf(v1, w1);
        v2 = cmulf(v2, w2);
        v3 = cmulf(v3, w3);
        float2 t0 = make_float2(v0.x + v2.x, v0.y + v2.y);
        float2 t1 = make_float2(v0.x - v2.x, v0.y - v2.y);
        float2 t2 = make_float2(v1.x + v3.x, v1.y + v3.y);
        float2 t3 = make_float2(v1.x - v3.x, v1.y - v3.y);
        int idxD = ((j >> s2) << (s2 + 2)) + jm;
        Y[idxD]          = make_float2(t0.x + t2.x, t0.y + t2.y);
        Y[idxD + Ns]     = make_float2(t1.x + t3.y, t1.y - t3.x);
        Y[idxD + 2 * Ns] = make_float2(t0.x - t2.x, t0.y - t2.y);
        Y[idxD + 3 * Ns] = make_float2(t1.x - t3.y, t1.y + t3.x);
        float2* tmp = X; X = Y; Y = tmp;
        __syncthreads();
    }

    float* amp = g_amp2_t + bh * L_;
    #pragma unroll
    for (int jj = 0; jj < 4; jj++) {
        int t = tid + jj * 256;
        float ac = X[t].x * (1.0f / (float)L_);
        atomicAdd(amp + t, ac * ac);
    }
}

// Top-35 per (b,h). blockIdx.x = bh + 16*which (0: corr amps, 1: tf norms).
__global__ void __launch_bounds__(256) topk_kernel(const float* __restrict__ tfq) {
    int bh    = blockIdx.x & 15;
    int which = blockIdx.x >> 4;
    int tid = threadIdx.x;
    int lane = tid & 31, wrp = tid >> 5;

    float v[4];
    if (which == 0) {
        #pragma unroll
        for (int jj = 0; jj < 4; jj++)
            v[jj] = g_amp2_t[bh * L_ + tid + jj * 256];
    } else {
        int b = bh >> 3, h = bh & 7;
        #pragma unroll
        for (int jj = 0; jj < 4; jj++) {
            int l = tid + jj * 256;
            const float4* p = (const float4*)(tfq + (((size_t)(b * L_ + l) * H_ + h) * E_));
            float s = 0.f;
            #pragma unroll
            for (int j = 0; j < 16; j++) {
                float4 x = p[j];
                s += x.x * x.x + x.y * x.y + x.z * x.z + x.w * x.w;
            }
            v[jj] = s;
        }
    }

    __shared__ float sv[8];
    __shared__ int   si[8];

    for (int iter = 0; iter < NT_; iter++) {
        float best = v[0];
        int   bi   = tid;
        #pragma unroll
        for (int jj = 1; jj < 4; jj++) {
            if (v[jj] > best) { best = v[jj]; bi = tid + jj * 256; }
        }
        #pragma unroll
        for (int off = 16; off > 0; off >>= 1) {
            float ov = __shfl_down_sync(0xffffffffu, best, off);
            int   oi = __shfl_down_sync(0xffffffffu, bi,   off);
            if (ov > best || (ov == best && oi < bi)) { best = ov; bi = oi; }
        }
        if (lane == 0) { sv[wrp] = best; si[wrp] = bi; }
        __syncthreads();
        float wv = sv[0]; int wi = si[0];
        #pragma unroll
        for (int w = 1; w < 8; w++) {
            if (sv[w] > wv || (sv[w] == wv && si[w] < wi)) { wv = sv[w]; wi = si[w]; }
        }
        if (tid == 0) g_selidx[bh * NS_ + which * NT_ + iter] = wi;
        if ((wi & 255) == tid) v[wi >> 8] = -1.0f;
        __syncthreads();
    }
}

// Gathered U columns + bias row: usel[bh][i][d] = sum_m W[m, c_i] * V[b,m,h,d],
// row 70: sum_m bias[m]*V[b,m,h,d]. m-chunk = 32 rows, grid (32, 16), 512 threads
// => 512 blocks (3.5/SM) to hide the L2-latency-bound scattered W gather.
__global__ void __launch_bounds__(512) usel_kernel(const float* __restrict__ W,
                                                   const float* __restrict__ bias,
                                                   const float* __restrict__ V) {
    int bh = blockIdx.y, b = bh >> 3, h = bh & 7;
    int m0 = blockIdx.x * 32;
    __shared__ float ws[71][32];
    __shared__ float vs[32][64];
    __shared__ int   cs_[NS_];
    int tid = threadIdx.x;

    if (tid < NS_) {
        cs_[tid] = g_selidx[bh * NS_ + tid] + ((tid >= NT_) ? L_ : 0);
    }
    // V tile: 32 rows x 64 = 512 float4, one per thread, coalesced
    {
        const float4* vsrc = (const float4*)(V + (((size_t)(b * L_ + m0) * H_) + h) * E_);
        int mm = tid >> 4, c4 = tid & 15;
        ((float4*)vs)[tid] = vsrc[(size_t)mm * 128 + c4];
    }
    __syncthreads();   // cs_ ready before gather

    // W gather: 71*32 = 2272 scattered loads over 512 threads (4-5 each, independent)
    for (int idx = tid; idx < 71 * 32; idx += 512) {
        int i = idx >> 5, mm = idx & 31;
        float v;
        if (i < NS_) {
            v = __ldg(&W[(size_t)(m0 + mm) * (2 * L_) + cs_[i]]);
        } else {
            v = bias[m0 + mm];
        }
        ws[i][mm] = v;
    }
    __syncthreads();

    int d = tid & 63, ig = tid >> 6;   // 8 i-groups
    float acc[9];
    #pragma unroll
    for (int kk2 = 0; kk2 < 9; kk2++) acc[kk2] = 0.f;

    #pragma unroll 4
    for (int mm = 0; mm < 32; mm++) {
        float v = vs[mm][d];
        #pragma unroll
        for (int kk2 = 0; kk2 < 9; kk2++) {
            int i = ig + kk2 * 8;
            if (i < 71) acc[kk2] += ws[i][mm] * v;
        }
    }
    #pragma unroll
    for (int kk2 = 0; kk2 < 9; kk2++) {
        int i = ig + kk2 * 8;
        if (i < 71) atomicAdd(&g_usel[(size_t)(bh * 71 + i) * E_ + d], acc[kk2]);
    }
}

// Fused scores + softmax + combine. One block = 16 l values of one (b,h),
// 128 threads, grid (64, 16) = 1024 blocks.
// Phase 1: 8 groups of 16 threads = (half, iseg 0..3); two-pass over the e
//   dimension (r held 8 float4 at a time) to keep registers low.
// Phase 2: 8 groups x 2 l each; lane16 covers d (coalesced float4 per lane);
//   us rows read directly from L2-hot g_usel (no smem staging).
__global__ void __launch_bounds__(128) fused_kernel(const float* __restrict__ tfq,
                                                    const float* __restrict__ q,
                                                    const float* __restrict__ kk,
                                                    float* __restrict__ out) {
    int bh = blockIdx.y, b = bh >> 3, h = bh & 7;
    int tid = threadIdx.x;
    int lane16 = tid & 15;
    int g = tid >> 4;               // 8 groups of 16

    __shared__ float qsel[NS_ * E_];    // selected query rows
    __shared__ float s[NS_][16];        // scores for this l-tile

    for (int idx = tid; idx < NS_ * E_; idx += 128) {
        int i = idx >> 6, e = idx & 63;
        int src = g_selidx[bh * NS_ + i];
        const float* sp = (i < NT_) ? q : tfq;
        qsel[idx] = sp[(((size_t)(b * L_ + src) * H_) + h) * E_ + e];
    }
    __syncthreads();

    // ---- phase 1: scores ----
    {
        int half = g >> 2;              // 0: vs keys, 1: vs tf_queries
        int iseg = g & 3;
        int i0 = iseg * 9;
        int cnt = (i0 + 9 < NT_) ? 9 : (NT_ - i0);   // 9,9,9,8
        int l = blockIdx.x * 16 + lane16;

        const float4* row = (const float4*)(((half == 0) ? kk : tfq)
                            + (((size_t)(b * L_ + l) * H_) + h) * E_);
        float part[9];
        #pragma unroll
        for (int ii = 0; ii < 9; ii++) part[ii] = 0.f;

        #pragma unroll
        for (int jh = 0; jh < 2; jh++) {
            float4 r[8];
            #pragma unroll
            for (int j = 0; j < 8; j++) r[j] = row[jh * 8 + j];

            for (int ii = 0; ii < cnt; ii++) {
                const float4* qr = (const float4*)&qsel[(half * NT_ + i0 + ii) * E_ + jh * 32];
                float s0 = 0.f, s1 = 0.f;
                #pragma unroll
                for (int j = 0; j < 4; j++) {
                    float4 qa = qr[j];
                    float4 qb = qr[j + 4];
                    s0 += qa.x * r[j].x + qa.y * r[j].y + qa.z * r[j].z + qa.w * r[j].w;
                    s1 += qb.x * r[j + 4].x + qb.y * r[j + 4].y + qb.z * r[j + 4].z + qb.w * r[j + 4].w;
                }
                part[ii] += s0 + s1;
            }
        }
        for (int ii = 0; ii < cnt; ii++)
            s[half * NT_ + i0 + ii][lane16] = part[ii] * SCALE_;
    }
    __syncthreads();

    // ---- phase 2: softmax + combine (8 groups x 2 l; lane16 -> d) ----
    {
        const float* us = g_usel + (size_t)bh * 71 * E_;
        const float4* bv = (const float4*)(us + NS_ * E_) + lane16;
        float4 bb = *bv;

        #pragma unroll
        for (int ll = 0; ll < 2; ll++) {
            int lt = g * 2 + ll;            // 0..15 within tile
            int l = blockIdx.x * 16 + lt;

            float mx = -1e30f;
            #pragma unroll
            for (int i = 0; i < NS_; i++) mx = fmaxf(mx, s[i][lt]);

            float4 acc = make_float4(0.f, 0.f, 0.f, 0.f);
            float ssum = 0.f;

            for (int i = 0; i < NS_; i++) {
                float p = __expf(s[i][lt] - mx);
                ssum += p;
                float4 u = ((const float4*)(us + i * E_))[lane16];
                acc.x += p * u.x; acc.y += p * u.y;
                acc.z += p * u.z; acc.w += p * u.w;
            }
            float inv = 1.f / ssum;
            float4* op = (float4*)(out + (((size_t)(b * L_ + l) * H_) + h) * E_) + lane16;
            *op = make_float4(acc.x * inv + bb.x, acc.y * inv + bb.y,
                              acc.z * inv + bb.z, acc.w * inv + bb.w);
        }
    }
}

extern "C" void kernel_launch(void* const* d_in, const int* in_sizes, int n_in,
                              void* d_out, int out_size) {
    const float* tfq  = (const float*)d_in[0];
    const float* q    = (const float*)d_in[1];
    const float* k    = (const float*)d_in[2];
    const float* v    = (const float*)d_in[3];
    // d_in[4] = mask (unused)
    const float* W    = (const float*)d_in[5];
    const float* bias = (const float*)d_in[6];
    float* out = (float*)d_out;

    zero_kernel<<<(BH_ * 71 * E_ + 255) / 256, 256>>>();
    corr_fft_kernel<<<BH_ * E_, 256>>>(q, k);
    topk_kernel<<<32, 256>>>(tfq);
    usel_kernel<<<dim3(32, BH_), 512>>>(W, bias, v);
    fused_kernel<<<dim3(64, BH_), 128>>>(tfq, q, k, out);
}